// round 17
// baseline (speedup 1.0000x reference)
#include <cuda_runtime.h>
#include <cuda_bf16.h>
#include <math.h>
#include <stdint.h>

// ---------------------------------------------------------------------------
// SimplifiedMultiHeadAttention  (B=2, S=2048, D=768, H=12, Dh=64)
// d_out = [output (B,S,768) fp32][attn_weights (B,H,S,S) fp32]
// All GEMMs mma.sync bf16 hi/lo x3, cp.async pipelined, max-free softmax,
// interleaved bf16 P' handoff.  This round: 64x64 warp tiles (4 warps/CTA)
// in proj/scores/outproj to halve LDSM pressure on the tensor pipe.
// ---------------------------------------------------------------------------

#define MD   768
#define NH   12
#define HD   64
#define BSZ  2
#define SEQ  2048
#define BH   (BSZ*NH)
#define MTOK (BSZ*SEQ)
#define OUT_ELEMS  (MTOK*MD)

// -------------------- scratch (static __device__) --------------------------
__device__ __nv_bfloat16 g_xqh[MTOK*MD], g_xql[MTOK*MD];
__device__ __nv_bfloat16 g_xkh[MTOK*MD], g_xkl[MTOK*MD];
__device__ __nv_bfloat16 g_xvh[MTOK*MD], g_xvl[MTOK*MD];
__device__ __nv_bfloat16 g_wqh[MD*MD], g_wql[MD*MD];
__device__ __nv_bfloat16 g_wkh[MD*MD], g_wkl[MD*MD];
__device__ __nv_bfloat16 g_wvh[MD*MD], g_wvl[MD*MD];
__device__ __nv_bfloat16 g_woh[MD*MD], g_wol[MD*MD];
__device__ __nv_bfloat16 g_qh[BH*SEQ*HD], g_ql[BH*SEQ*HD];
__device__ __nv_bfloat16 g_kh[BH*SEQ*HD], g_kl[BH*SEQ*HD];
__device__ float         g_vp [BH*SEQ*HD];
__device__ __nv_bfloat16 g_vth[BH*HD*SEQ], g_vtl[BH*HD*SEQ];
__device__ __nv_bfloat16 g_cth[MTOK*MD], g_ctl[MTOK*MD];
__device__ float g_psum  [(size_t)BH*SEQ*32];   // per (row, 64-col block) expsum
__device__ float g_rscale[(size_t)BH*SEQ];      // 1 / rowsum

// -------------------- helpers ----------------------------------------------
__device__ __forceinline__ uint32_t smem_u32(const void* p) {
    uint32_t a;
    asm("{ .reg .u64 t; cvta.to.shared.u64 t, %1; cvt.u32.u64 %0, t; }" : "=r"(a) : "l"(p));
    return a;
}
__device__ __forceinline__ void ldsm4(uint32_t r[4], uint32_t addr) {
    asm volatile("ldmatrix.sync.aligned.m8n8.x4.shared.b16 {%0,%1,%2,%3}, [%4];"
        : "=r"(r[0]), "=r"(r[1]), "=r"(r[2]), "=r"(r[3]) : "r"(addr));
}
__device__ __forceinline__ void mma_bf16(float* c, const uint32_t* a, uint32_t b0, uint32_t b1) {
    asm volatile("mma.sync.aligned.m16n8k16.row.col.f32.bf16.bf16.f32 "
        "{%0,%1,%2,%3}, {%4,%5,%6,%7}, {%8,%9}, {%0,%1,%2,%3};"
        : "+f"(c[0]), "+f"(c[1]), "+f"(c[2]), "+f"(c[3])
        : "r"(a[0]), "r"(a[1]), "r"(a[2]), "r"(a[3]), "r"(b0), "r"(b1));
}
__device__ __forceinline__ void cp16(uint32_t saddr, const void* g) {
    asm volatile("cp.async.cg.shared.global [%0], [%1], 16;" :: "r"(saddr), "l"(g));
}
#define CP_COMMIT() asm volatile("cp.async.commit_group;")
#define CP_WAIT(n)  asm volatile("cp.async.wait_group %0;" :: "n"(n))

__device__ __forceinline__ void bf_split(float v, unsigned short& h, unsigned short& l) {
    __nv_bfloat16 hh = __float2bfloat16(v);
    float r = v - __bfloat162float(hh);
    __nv_bfloat16 ll = __float2bfloat16(r);
    h = __bfloat16_as_ushort(hh);
    l = __bfloat16_as_ushort(ll);
}
__device__ __forceinline__ uint32_t pack2(unsigned short a, unsigned short b) {
    return (uint32_t)a | ((uint32_t)b << 16);
}

#define TSTR 72   // 64-k tiles: 144B row stride (ldmatrix conflict-free)

// ---------------------------------------------------------------------------
// Kernel 0: batched hi/lo splits.
// ---------------------------------------------------------------------------
__global__ __launch_bounds__(256) void splitX_kernel(
    const float* __restrict__ q, const float* __restrict__ k, const float* __restrict__ v)
{
    const float* src; __nv_bfloat16 *dh, *dl;
    switch (blockIdx.y) {
        case 0:  src = q; dh = g_xqh; dl = g_xql; break;
        case 1:  src = k; dh = g_xkh; dl = g_xkl; break;
        default: src = v; dh = g_xvh; dl = g_xvl; break;
    }
    int i = (blockIdx.x * 256 + threadIdx.x) * 4;
    float4 x = *(const float4*)(src + i);
    unsigned short hs[4], ls[4];
    bf_split(x.x, hs[0], ls[0]); bf_split(x.y, hs[1], ls[1]);
    bf_split(x.z, hs[2], ls[2]); bf_split(x.w, hs[3], ls[3]);
    *(uint2*)(dh + i) = make_uint2(pack2(hs[0],hs[1]), pack2(hs[2],hs[3]));
    *(uint2*)(dl + i) = make_uint2(pack2(ls[0],ls[1]), pack2(ls[2],ls[3]));
}
__global__ __launch_bounds__(256) void splitW_kernel(
    const float* __restrict__ wq, const float* __restrict__ wk,
    const float* __restrict__ wv, const float* __restrict__ wo)
{
    const float* src; __nv_bfloat16 *dh, *dl;
    switch (blockIdx.y) {
        case 0:  src = wq; dh = g_wqh; dl = g_wql; break;
        case 1:  src = wk; dh = g_wkh; dl = g_wkl; break;
        case 2:  src = wv; dh = g_wvh; dl = g_wvl; break;
        default: src = wo; dh = g_woh; dl = g_wol; break;
    }
    int i = (blockIdx.x * 256 + threadIdx.x) * 4;
    float4 x = *(const float4*)(src + i);
    unsigned short hs[4], ls[4];
    bf_split(x.x, hs[0], ls[0]); bf_split(x.y, hs[1], ls[1]);
    bf_split(x.z, hs[2], ls[2]); bf_split(x.w, hs[3], ls[3]);
    *(uint2*)(dh + i) = make_uint2(pack2(hs[0],hs[1]), pack2(hs[2],hs[3]));
    *(uint2*)(dl + i) = make_uint2(pack2(ls[0],ls[1]), pack2(ls[2],ls[3]));
}

// ---------------------------------------------------------------------------
// Kernel 1: Q/K/V projections.  128x128 CTA tile, 4 warps of 64x64,
// 32-k chunks (24), stride-80 tiles, 2-stage cp.async.
// Stage: AH 0 | AL 10240 | BH 20480 | BL 30720 (40960 B) x2 = 81920 B.
// ---------------------------------------------------------------------------
#define PSTG 40960
__global__ __launch_bounds__(128) void projmma_kernel(
    const float* __restrict__ wqb, const float* __restrict__ wkb,
    const float* __restrict__ wvb)
{
    extern __shared__ char sm[];
    const uint32_t sb = smem_u32(sm);
    const int tid = threadIdx.x, wid = tid >> 5, lane = tid & 31;
    const int n0 = blockIdx.x * 128, m0 = blockIdx.y * 128, z = blockIdx.z;

    const __nv_bfloat16 *Ah, *Al, *Bh, *Bl;
    const float* bias;
    if (z == 0)      { Ah = g_xqh; Al = g_xql; Bh = g_wqh; Bl = g_wql; bias = wqb; }
    else if (z == 1) { Ah = g_xkh; Al = g_xkl; Bh = g_wkh; Bl = g_wkl; bias = wkb; }
    else             { Ah = g_xvh; Al = g_xvl; Bh = g_wvh; Bl = g_wvl; bias = wvb; }

    auto load_chunk = [&](int ck, int st) {
        const int k0 = ck * 32;
        const uint32_t bo = sb + st * PSTG;
        const __nv_bfloat16* s0 = Ah + (size_t)m0 * MD + k0;
        const __nv_bfloat16* s1 = Al + (size_t)m0 * MD + k0;
        const __nv_bfloat16* s2 = Bh + (size_t)n0 * MD + k0;
        const __nv_bfloat16* s3 = Bl + (size_t)n0 * MD + k0;
        for (int i = tid; i < 512; i += 128) {       // 128 rows x 4 segs(16B)
            const int r = i >> 2, sg = i & 3;
            const size_t go = (size_t)r * MD + sg * 8;
            const uint32_t so = r * 80 + sg * 16;
            cp16(bo + 0     + so, s0 + go);
            cp16(bo + 10240 + so, s1 + go);
            cp16(bo + 20480 + so, s2 + go);
            cp16(bo + 30720 + so, s3 + go);
        }
        CP_COMMIT();
    };

    const int wm = wid >> 1, wn = wid & 1;           // 2x2 warps of 64x64
    float c[4][8][4];
    #pragma unroll
    for (int mt = 0; mt < 4; mt++)
        #pragma unroll
        for (int nt = 0; nt < 8; nt++)
            #pragma unroll
            for (int r = 0; r < 4; r++) c[mt][nt][r] = 0.f;

    const int arow = lane & 15, ahalf = (lane >> 4) * 8;

    load_chunk(0, 0);
    for (int ck = 0; ck < 24; ck++) {
        const uint32_t bo = sb + (ck & 1) * PSTG;
        if (ck < 23) { load_chunk(ck + 1, (ck + 1) & 1); CP_WAIT(1); }
        else         { CP_WAIT(0); }
        __syncthreads();
        #pragma unroll
        for (int pass = 0; pass < 3; pass++) {
            const uint32_t aoff = bo + (pass == 2 ? 10240 : 0);
            const uint32_t boff = bo + (pass == 1 ? 30720 : 20480);
            #pragma unroll
            for (int ks = 0; ks < 2; ks++) {
                uint32_t a[4][4], bb[4][4];
                #pragma unroll
                for (int mt = 0; mt < 4; mt++)
                    ldsm4(a[mt], aoff + (wm*64 + mt*16 + arow) * 80 + (ks*16 + ahalf) * 2);
                #pragma unroll
                for (int np = 0; np < 4; np++)
                    ldsm4(bb[np], boff + (wn*64 + np*16 + arow) * 80 + (ks*16 + ahalf) * 2);
                #pragma unroll
                for (int mt = 0; mt < 4; mt++)
                    #pragma unroll
                    for (int nt = 0; nt < 8; nt++)
                        mma_bf16(c[mt][nt], a[mt], bb[nt>>1][nt&1], bb[nt>>1][(nt&1)+2]);
            }
        }
        __syncthreads();
    }

    const int qr = lane >> 2, qc = (lane & 3) * 2;
    #pragma unroll
    for (int mt = 0; mt < 4; mt++)
        #pragma unroll
        for (int hh = 0; hh < 2; hh++) {
            const int row = wm*64 + mt*16 + hh*8 + qr;
            const int m = m0 + row, b = m >> 11, s = m & (SEQ - 1);
            #pragma unroll
            for (int nt = 0; nt < 8; nt++) {
                const int n = n0 + wn*64 + nt*8 + qc;
                const float v0 = c[mt][nt][hh*2+0] + bias[n];
                const float v1 = c[mt][nt][hh*2+1] + bias[n+1];
                const int h = n >> 6, d = n & 63;
                const size_t base = ((size_t)(b * NH + h) * SEQ + s) * HD + d;
                if (z == 2) {
                    *(float2*)(g_vp + base) = make_float2(v0, v1);
                } else {
                    unsigned short h0, l0, h1, l1;
                    bf_split(v0, h0, l0); bf_split(v1, h1, l1);
                    if (z == 0) {
                        *(uint32_t*)(g_qh + base) = pack2(h0, h1);
                        *(uint32_t*)(g_ql + base) = pack2(l0, l1);
                    } else {
                        *(uint32_t*)(g_kh + base) = pack2(h0, h1);
                        *(uint32_t*)(g_kl + base) = pack2(l0, l1);
                    }
                }
            }
        }
}

// ---------------------------------------------------------------------------
// Kernel 2: transpose V per head + split hi/lo -> g_vth/g_vtl [bh][d][s]
// ---------------------------------------------------------------------------
__global__ __launch_bounds__(256) void vtrans_kernel()
{
    const int s0 = blockIdx.x * 64, bh = blockIdx.y;
    __shared__ float t[64][65];
    const int tid = threadIdx.x;
    #pragma unroll
    for (int e = 0; e < 4; e++) {
        int i = tid + e * 256;
        int r = i >> 4, c4 = (i & 15) * 4;
        float4 v = *(const float4*)(g_vp + ((size_t)bh * SEQ + s0 + r) * HD + c4);
        t[r][c4+0] = v.x; t[r][c4+1] = v.y; t[r][c4+2] = v.z; t[r][c4+3] = v.w;
    }
    __syncthreads();
    #pragma unroll
    for (int e = 0; e < 4; e++) {
        int i = tid + e * 256;
        int d = i >> 4, sl = (i & 15) * 4;
        unsigned short hs[4], ls[4];
        #pragma unroll
        for (int j = 0; j < 4; j++) bf_split(t[sl + j][d], hs[j], ls[j]);
        size_t base = ((size_t)bh * HD + d) * SEQ + s0 + sl;
        *(uint2*)(g_vth + base) = make_uint2(pack2(hs[0],hs[1]), pack2(hs[2],hs[3]));
        *(uint2*)(g_vtl + base) = make_uint2(pack2(ls[0],ls[1]), pack2(ls[2],ls[3]));
    }
}

// ---------------------------------------------------------------------------
// Kernel 3: scores.  128x128 CTA tile, 4 warps of 64x64.  P' = exp(s/8)
// (max-free), stored interleaved bf16 hi/lo: row = 8192 B, 64-col chunk ch:
// hi at ch*256, lo at ch*256+128.  Partial sums per (row, 64-col block).
// smem: QH 0 | QL 18432 | KH 36864 | KL 55296  (73728 B)
// ---------------------------------------------------------------------------
__global__ __launch_bounds__(128) void scores_kernel(float* __restrict__ attn)
{
    extern __shared__ char sm[];
    const uint32_t sb = smem_u32(sm);
    const int tid = threadIdx.x, wid = tid >> 5, lane = tid & 31;
    const int bh = blockIdx.z, m0 = blockIdx.y * 128, n0 = blockIdx.x * 128;
    char* attnb = (char*)attn;

    {
        const __nv_bfloat16* qh = g_qh + ((size_t)bh * SEQ + m0) * HD;
        const __nv_bfloat16* kh = g_kh + ((size_t)bh * SEQ + n0) * HD;
        const __nv_bfloat16* ql = g_ql + ((size_t)bh * SEQ + m0) * HD;
        const __nv_bfloat16* kl = g_kl + ((size_t)bh * SEQ + n0) * HD;
        for (int i = tid; i < 1024; i += 128) {
            const int r = i >> 3, sg = i & 7;
            const size_t go = (size_t)r * HD + sg * 8;
            const uint32_t so = r * (TSTR*2) + sg * 16;
            cp16(sb + 0     + so, qh + go);
            cp16(sb + 36864 + so, kh + go);
        }
        CP_COMMIT();
        for (int i = tid; i < 1024; i += 128) {
            const int r = i >> 3, sg = i & 7;
            const size_t go = (size_t)r * HD + sg * 8;
            const uint32_t so = r * (TSTR*2) + sg * 16;
            cp16(sb + 18432 + so, ql + go);
            cp16(sb + 55296 + so, kl + go);
        }
        CP_COMMIT();
    }

    const int wm = wid >> 1, wn = wid & 1;          // 2x2 warps of 64x64
    float c[4][8][4];
    #pragma unroll
    for (int mt = 0; mt < 4; mt++)
        #pragma unroll
        for (int nt = 0; nt < 8; nt++)
            #pragma unroll
            for (int r = 0; r < 4; r++) c[mt][nt][r] = 0.f;

    const int arow = lane & 15, ahalf = (lane >> 4) * 8;

    auto do_pass = [&](uint32_t aoff, uint32_t boff) {
        #pragma unroll
        for (int ks = 0; ks < 4; ks++) {
            uint32_t a[4][4], bb[4][4];
            #pragma unroll
            for (int mt = 0; mt < 4; mt++)
                ldsm4(a[mt], aoff + ((wm*64 + mt*16 + arow) * TSTR + ks*16 + ahalf) * 2);
            #pragma unroll
            for (int np = 0; np < 4; np++)
                ldsm4(bb[np], boff + ((wn*64 + np*16 + arow) * TSTR + ks*16 + ahalf) * 2);
            #pragma unroll
            for (int mt = 0; mt < 4; mt++)
                #pragma unroll
                for (int nt = 0; nt < 8; nt++)
                    mma_bf16(c[mt][nt], a[mt], bb[nt>>1][nt&1], bb[nt>>1][(nt&1)+2]);
        }
    };

    CP_WAIT(1);
    __syncthreads();
    do_pass(sb + 0, sb + 36864);          // hh
    CP_WAIT(0);
    __syncthreads();
    do_pass(sb + 0, sb + 55296);          // h*l
    do_pass(sb + 18432, sb + 36864);      // l*h

    // epilogue: exp (no max), interleaved bf16 hi/lo store, partial sums
    const int qr = lane >> 2, qc = (lane & 3) * 2;
    const int ch = blockIdx.x * 2 + wn;   // 64-col block id (0..31)
    #pragma unroll
    for (int mt = 0; mt < 4; mt++)
        #pragma unroll
        for (int hh = 0; hh < 2; hh++) {
            const int row = wm*64 + mt*16 + hh*8 + qr;
            const size_t rowb = (size_t)(bh*SEQ + m0 + row) * 8192;
            char* base0 = attnb + rowb + (size_t)ch * 256;
            float sum = 0.f;
            #pragma unroll
            for (int nt = 0; nt < 8; nt++) {
                const float p0 = __expf(c[mt][nt][hh*2+0] * 0.125f);
                const float p1 = __expf(c[mt][nt][hh*2+1] * 0.125f);
                sum += p0 + p1;
                const int w = nt*8 + qc;                     // 0..63
                unsigned short h0, l0, h1, l1;
                bf_split(p0, h0, l0); bf_split(p1, h1, l1);
                *(uint32_t*)(base0 + w*2)       = pack2(h0, h1);
                *(uint32_t*)(base0 + w*2 + 128) = pack2(l0, l1);
            }
            sum += __shfl_xor_sync(0xffffffffu, sum, 1);
            sum += __shfl_xor_sync(0xffffffffu, sum, 2);
            if ((lane & 3) == 0)
                g_psum[((size_t)bh*SEQ + m0 + row) * 32 + ch] = sum;
        }
}

// ---------------------------------------------------------------------------
// Kernel 4: merge 32 partial sums per row -> 1/rowsum
// ---------------------------------------------------------------------------
__global__ __launch_bounds__(256) void merge_kernel()
{
    const int tid = threadIdx.x;
    const int row = blockIdx.x * 32 + (tid >> 3);
    const int sub = tid & 7;
    const float* p = g_psum + (size_t)row * 32 + sub * 4;
    float S = p[0] + p[1] + p[2] + p[3];
    #pragma unroll
    for (int o = 1; o < 8; o <<= 1) S += __shfl_xor_sync(0xffffffffu, S, o);
    if (sub == 0) g_rscale[row] = 1.0f / S;
}

// ---------------------------------------------------------------------------
// Kernel 5: context (unchanged from round 16).  Fully-async loads; mma 3-pass
// accumulates unscaled; per-row 1/S at epilogue; final fp32 attn written from
// smem hi/lo in-place.
// Stage: PH 0 | PL 18432 | VH 36864 | VL 46080  (55296 B x2)
// ---------------------------------------------------------------------------
#define CSTG 55296
__global__ __launch_bounds__(256) void context_kernel(float* __restrict__ attn)
{
    extern __shared__ char sm[];
    const uint32_t sb = smem_u32(sm);
    const int tid = threadIdx.x, wid = tid >> 5, lane = tid & 31;
    const int m0 = blockIdx.x * 128, bh = blockIdx.y;
    char* attnb = (char*)attn;
    const size_t row0 = (size_t)bh * SEQ + m0;

    const int prow = tid >> 1;
    const int cbase = (tid & 1) * 32;
    const float srow = g_rscale[row0 + prow];

    auto load_pv = [&](int ch, int st) {
        const uint32_t bo = sb + st * CSTG;
        for (int i = tid; i < 1024; i += 256) {
            const int r = i >> 3, sg = i & 7;
            const char* g = attnb + (row0 + r) * 8192 + (size_t)ch * 256 + sg * 16;
            cp16(bo + 0     + r * 144 + sg * 16, g);
            cp16(bo + 18432 + r * 144 + sg * 16, g + 128);
        }
        for (int i = tid; i < 512; i += 256) {
            const int d = i >> 3, sg = i & 7;
            const size_t ga = ((size_t)bh * HD + d) * SEQ + ch * 64 + sg * 8;
            cp16(bo + 36864 + d * 144 + sg * 16, g_vth + ga);
            cp16(bo + 46080 + d * 144 + sg * 16, g_vtl + ga);
        }
        CP_COMMIT();
    };

    const int wm = wid >> 1, wn = wid & 1;
    float c[2][4][4];
    #pragma unroll
    for (int mt = 0; mt < 2; mt++)
        #pragma unroll
        for (int nt = 0; nt < 4; nt++)
            #pragma unroll
            for (int r = 0; r < 4; r++) c[mt][nt][r] = 0.f;

    const int arow = lane & 15, ahalf = (lane >> 4) * 8;

    load_pv(0, 0);
    for (int ch = 0; ch < 32; ch++) {
        const int st = ch & 1;
        if (ch < 31) { load_pv(ch + 1, st ^ 1); CP_WAIT(1); }
        else         { CP_WAIT(0); }
        __syncthreads();

        const uint32_t bo = sb + st * CSTG;
        char* stp = sm + st * CSTG;
        #pragma unroll
        for (int pass = 0; pass < 3; pass++) {
            const uint32_t aoff = bo + (pass == 2 ? 18432 : 0);
            const uint32_t boff = bo + (pass == 1 ? 46080 : 36864);
            #pragma unroll
            for (int ks = 0; ks < 4; ks++) {
                uint32_t a[2][4], bb[2][4];
                #pragma unroll
                for (int mt = 0; mt < 2; mt++)
                    ldsm4(a[mt], aoff + (wm*32 + mt*16 + arow) * 144 + (ks*16 + ahalf) * 2);
                #pragma unroll
                for (int np = 0; np < 2; np++)
                    ldsm4(bb[np], boff + (wn*32 + np*16 + arow) * 144 + (ks*16 + ahalf) * 2);
                #pragma unroll
                for (int mt = 0; mt < 2; mt++)
                    #pragma unroll
                    for (int nt = 0; nt < 4; nt++)
                        mma_bf16(c[mt][nt], a[mt], bb[nt>>1][nt&1], bb[nt>>1][(nt&1)+2]);
            }
        }

        // final fp32 attn from smem hi/lo (overwrites this chunk's own bytes)
        {
            float* dst = attn + (row0 + prow) * SEQ + ch * 64 + cbase;
            const char* ph = stp + 0     + prow * 144 + cbase * 2;
            const char* pl = stp + 18432 + prow * 144 + cbase * 2;
            #pragma unroll
            for (int j = 0; j < 8; j++) {
                uint2 uh = *(const uint2*)(ph + j * 8);
                uint2 ul = *(const uint2*)(pl + j * 8);
                float4 o;
                o.x = (__uint_as_float(uh.x << 16)          + __uint_as_float(ul.x << 16))          * srow;
                o.y = (__uint_as_float(uh.x & 0xffff0000u)  + __uint_as_float(ul.x & 0xffff0000u))  * srow;
                o.z = (__uint_as_float(uh.y << 16)          + __uint_as_float(ul.y << 16))          * srow;
                o.w = (__uint_as_float(uh.y & 0xffff0000u)  + __uint_as_float(ul.y & 0xffff0000u))  * srow;
                *(float4*)(dst + j * 4) = o;
            }
        }
        __syncthreads();
    }

    // epilogue: ctx = c * (1/rowsum) -> hi/lo bf16 [B,S,768]
    const int b = bh / NH, h = bh % NH;
    const int qr = lane >> 2, qc = (lane & 3) * 2;
    #pragma unroll
    for (int mt = 0; mt < 2; mt++)
        #pragma unroll
        for (int hh = 0; hh < 2; hh++) {
            const int row = wm*32 + mt*16 + hh*8 + qr;
            const float sr = g_rscale[row0 + row];
            const size_t base = ((size_t)b * SEQ + m0 + row) * MD + h * HD;
            #pragma unroll
            for (int nt = 0; nt < 4; nt++) {
                unsigned short h0, l0, h1, l1;
                bf_split(c[mt][nt][hh*2+0] * sr, h0, l0);
                bf_split(c[mt][nt][hh*2+1] * sr, h1, l1);
                *(uint32_t*)(g_cth + base + wn*32 + nt*8 + qc) = pack2(h0, h1);
                *(uint32_t*)(g_ctl + base + wn*32 + nt*8 + qc) = pack2(l0, l1);
            }
        }
}

// ---------------------------------------------------------------------------
// Kernel 6: output projection.  128x128 CTA tile, 4 warps of 64x64,
// 32-k / stride-80 / 2-stage pipeline.
// ---------------------------------------------------------------------------
__global__ __launch_bounds__(128) void outproj_kernel(
    const float* __restrict__ wob, float* __restrict__ out)
{
    extern __shared__ char sm[];
    const uint32_t sb = smem_u32(sm);
    const int tid = threadIdx.x, wid = tid >> 5, lane = tid & 31;
    const int n0 = blockIdx.x * 128, m0 = blockIdx.y * 128;

    auto load_chunk = [&](int ck, int st) {
        const int k0 = ck * 32;
        const uint32_t bo = sb + st * PSTG;
        const __nv_bfloat16* s0 = g_cth + (size_t)m0 * MD + k0;
        const __nv_bfloat16* s1 = g_ctl + (size_t)m0 * MD + k0;
        const __nv_bfloat16* s2 = g_woh + (size_t)n0 * MD + k0;
        const __nv_bfloat16* s3 = g_wol + (size_t)n0 * MD + k0;
        for (int i = tid; i < 512; i += 128) {
            const int r = i >> 2, sg = i & 3;
            const size_t go = (size_t)r * MD + sg * 8;
            const uint32_t so = r * 80 + sg * 16;
            cp16(bo + 0     + so, s0 + go);
            cp16(bo + 10240 + so, s1 + go);
            cp16(bo + 20480 + so, s2 + go);
            cp16(bo + 30720 + so, s3 + go);
        }
        CP_COMMIT();
    };

    const int wm = wid >> 1, wn = wid & 1;
    float c[4][8][4];
    #pragma unroll
    for (int mt = 0; mt < 4; mt++)
        #pragma unroll
        for (int nt = 0; nt < 8; nt++)
            #pragma unroll
            for (int r = 0; r < 4; r++) c[mt][nt][r] = 0.f;

    const int arow = lane & 15, ahalf = (lane >> 4) * 8;

    load_chunk(0, 0);
    for (int ck = 0; ck < 24; ck++) {
        const uint32_t bo = sb + (ck & 1) * PSTG;
        if (ck < 23) { load_chunk(ck + 1, (ck + 1) & 1); CP_WAIT(1); }
        else         { CP_WAIT(0); }
        __syncthreads();
        #pragma unroll
        for (int pass = 0; pass < 3; pass++) {
            const uint32_t aoff = bo + (pass == 2 ? 10240 : 0);
            const uint32_t boff = bo + (pass == 1 ? 30720 : 20480);
            #pragma unroll
            for (int ks = 0; ks < 2; ks++) {
                uint32_t a[4][4], bb[4][4];
                #pragma unroll
                for (int mt = 0; mt < 4; mt++)
                    ldsm4(a[mt], aoff + (wm*64 + mt*16 + arow) * 80 + (ks*16 + ahalf) * 2);
                #pragma unroll
                for (int np = 0; np < 4; np++)
                    ldsm4(bb[np], boff + (wn*64 + np*16 + arow) * 80 + (ks*16 + ahalf) * 2);
                #pragma unroll
                for (int mt = 0; mt < 4; mt++)
                    #pragma unroll
                    for (int nt = 0; nt < 8; nt++)
                        mma_bf16(c[mt][nt], a[mt], bb[nt>>1][nt&1], bb[nt>>1][(nt&1)+2]);
            }
        }
        __syncthreads();
    }

    const int qr = lane >> 2, qc = (lane & 3) * 2;
    #pragma unroll
    for (int mt = 0; mt < 4; mt++)
        #pragma unroll
        for (int hh = 0; hh < 2; hh++) {
            const int m = m0 + wm*64 + mt*16 + hh*8 + qr;
            #pragma unroll
            for (int nt = 0; nt < 8; nt++) {
                const int n = n0 + wn*64 + nt*8 + qc;
                *(float2*)(out + (size_t)m * MD + n) =
                    make_float2(c[mt][nt][hh*2+0] + wob[n], c[mt][nt][hh*2+1] + wob[n+1]);
            }
        }
}

// ---------------------------------------------------------------------------
// Launcher
// ---------------------------------------------------------------------------
extern "C" void kernel_launch(void* const* d_in, const int* in_sizes, int n_in,
                              void* d_out, int out_size)
{
    const float* q   = (const float*)d_in[0];
    const float* k   = (const float*)d_in[1];
    const float* v   = (const float*)d_in[2];
    const float* wq  = (const float*)d_in[3];
    const float* wqb = (const float*)d_in[4];
    const float* wk  = (const float*)d_in[5];
    const float* wkb = (const float*)d_in[6];
    const float* wv  = (const float*)d_in[7];
    const float* wvb = (const float*)d_in[8];
    const float* wo  = (const float*)d_in[9];
    const float* wob = (const float*)d_in[10];
    float* out  = (float*)d_out;
    float* attn = out + OUT_ELEMS;

    const int PROJ_SMEM = 2 * PSTG;   // 81920
    const int SC_SMEM   = 73728;
    const int CTX_SMEM  = 2 * CSTG;   // 110592
    cudaFuncSetAttribute(projmma_kernel, cudaFuncAttributeMaxDynamicSharedMemorySize, PROJ_SMEM);
    cudaFuncSetAttribute(scores_kernel,  cudaFuncAttributeMaxDynamicSharedMemorySize, SC_SMEM);
    cudaFuncSetAttribute(context_kernel, cudaFuncAttributeMaxDynamicSharedMemorySize, CTX_SMEM);
    cudaFuncSetAttribute(outproj_kernel, cudaFuncAttributeMaxDynamicSharedMemorySize, PROJ_SMEM);

    splitX_kernel<<<dim3(MTOK*MD/1024, 3), 256>>>(q, k, v);
    splitW_kernel<<<dim3(MD*MD/1024, 4), 256>>>(wq, wk, wv, wo);

    projmma_kernel<<<dim3(MD/128, MTOK/128, 3), 128, PROJ_SMEM>>>(wqb, wkb, wvb);
    vtrans_kernel <<<dim3(SEQ/64, BH), 256>>>();
    scores_kernel <<<dim3(SEQ/128, SEQ/128, BH), 128, SC_SMEM>>>(attn);
    merge_kernel  <<<dim3(BH*SEQ/32), 256>>>();
    context_kernel<<<dim3(SEQ/128, BH), 256, CTX_SMEM>>>(attn);
    outproj_kernel<<<dim3(MD/128, MTOK/128), 128, PROJ_SMEM>>>(wob, out);
}